// round 14
// baseline (speedup 1.0000x reference)
#include <cuda_runtime.h>
#include <math.h>

// ---------------------------------------------------------------------------
// b=2, c=512, h=w=64 -> n=4096 points, d=64 features, 5x5 local cov.
// out[b] = concat(mu (64 ch), local cov (25 ch)) -> (2, 89, 64, 64) fp32.
//
//   K_yy+sigma I = L L^T     (blocked Cholesky NB=128, z-batched)
//   iL512_J = inverse of each 512x512 diagonal super-block of L
//            (recursive-doubling merges, z-batched over nodes: 4 launches)
//   X (in g_X2) = [K_xy ; ff^T] L^{-T} via 8 super-steps:
//       J>0: X[:,J] -= X2[:,<J] * L[J,<J]^T    (one K=J*512 GEMM)
//       X2[:,J] = X[:,J] * iL512_J^T           (one K-clipped GEMM)
//   mu = X2(0:4096) @ X2(4096:4160)^T          (split-K)
//   cov[p,q] = K_xx[p,q] - X2[p,:].X2[q,:]     (5x5 neighbors only;
//       local4_k tiles 4 p's per block, each q-row streamed once)
//
// GEMM inner loop: A-fragment is warp-broadcast; B-fragment split into two
// conflict-free float4s at cols tx*4 and tx*4+64 (no smem bank conflicts).
// ---------------------------------------------------------------------------

#define NPT   4096
#define MROWS 4224
#define NBLK  32
#define LNN   ((size_t)NPT * NPT)
#define XNN   ((size_t)MROWS * NPT)

__device__ float g_L  [2 * LNN];             // K_yy -> L (lower)
__device__ float g_LI [2 * LNN];             // iL128 diags + merge panels (lower)
__device__ float g_X  [2 * XNN];             // [K_xy ; ff^T ; 0], working
__device__ float g_X2 [2 * XNN];             // solved columns
__device__ float g_T  [2 * (size_t)1024 * 1024];  // tree temps
__device__ float g_XF [2 * (size_t)NPT * 512];
__device__ float g_MUP[2 * 8 * (size_t)NPT * 128];
__device__ float g_xn [2 * NPT];
__device__ float g_yn [2 * NPT];

// ---------------- prep kernels (z = batch) ----------------
__global__ void norms2_k(const float* __restrict__ x, const float* __restrict__ y,
                         float* __restrict__ xn, float* __restrict__ yn) {
    int b = blockIdx.z, sel = blockIdx.y;
    const float* v = (sel ? y : x) + (size_t)b * 512 * NPT;
    float* o = (sel ? yn : xn) + (size_t)b * NPT;
    int p = blockIdx.x * blockDim.x + threadIdx.x;
    float s = 0.f;
    for (int ch = 0; ch < 512; ch++) { float t = v[(size_t)ch * NPT + p]; s += t * t; }
    o[p] = sqrtf(s);
}

__global__ void transpose_k(const float* __restrict__ x, float* __restrict__ of) {
    int b = blockIdx.z;
    const float* v = x + (size_t)b * 512 * NPT;
    float* o = of + (size_t)b * NPT * 512;
    __shared__ float t[32][33];
    int pb = blockIdx.x * 32, cb = blockIdx.y * 32;
    for (int yy = threadIdx.y; yy < 32; yy += 8)
        t[yy][threadIdx.x] = v[(size_t)(cb + yy) * NPT + pb + threadIdx.x];
    __syncthreads();
    for (int yy = threadIdx.y; yy < 32; yy += 8)
        o[(size_t)(pb + yy) * 512 + cb + threadIdx.x] = t[threadIdx.x][yy];
}

__global__ void features_k(const float* __restrict__ pw, const float* __restrict__ pb,
                           float* __restrict__ X) {
    int b = blockIdx.z;
    int idx = blockIdx.x * blockDim.x + threadIdx.x;   // 4096*64
    int q = idx & 4095, dch = idx >> 12;
    float gx = (2.f * (float)(q & 63) + 1.f) * (1.f / 64.f) - 1.f;
    float gy = (2.f * (float)(q >> 6) + 1.f) * (1.f / 64.f) - 1.f;
    float ph = pw[dch * 2 + 0] * gx + pw[dch * 2 + 1] * gy + pb[dch];
    X[(size_t)b * XNN + LNN + (size_t)dch * NPT + q] = cosf(25.132741228718345f * ph);
}

// ---------------- fused Gram: K_yy (lower,+sigma) and K_xy in one launch ----
// grid (32, 64, 2): by<32 -> C=L, A=y, lower-only; by>=32 -> C=X, A=x, full.
__global__ void __launch_bounds__(256) gram2(const float* __restrict__ x,
        const float* __restrict__ y, float* __restrict__ Lout, float* __restrict__ Xout,
        const float* __restrict__ xn, const float* __restrict__ yn, float sigmaDiag) {
    int bx = blockIdx.x, byr = blockIdx.y, bz = blockIdx.z;
    int isYY = (byr < 32);
    int by = isYY ? byr : byr - 32;
    if (isYY && bx > by) return;
    const float* A = (isYY ? y : x) + (size_t)bz * 512 * NPT;
    const float* B = y + (size_t)bz * 512 * NPT;
    float* Cm = isYY ? (Lout + (size_t)bz * LNN) : (Xout + (size_t)bz * XNN);
    const float* na = (isYY ? yn : xn) + (size_t)bz * NPT;
    const float* nb = yn + (size_t)bz * NPT;
    __shared__ float As[8][128], Bs[8][128];
    int tid = threadIdx.x;
    int tx = tid & 15, ty = tid >> 4;
    const float* Ab = A + by * 128;
    const float* Bb = B + bx * 128;
    float acc[8][8];
    #pragma unroll
    for (int i = 0; i < 8; i++)
        #pragma unroll
        for (int j = 0; j < 8; j++) acc[i][j] = 0.f;
    int lr = tid >> 5;
    int lc = (tid & 31) << 2;
    for (int k0 = 0; k0 < 512; k0 += 8) {
        float4 av = *(const float4*)(Ab + (size_t)(k0 + lr) * NPT + lc);
        float4 bv = *(const float4*)(Bb + (size_t)(k0 + lr) * NPT + lc);
        *(float4*)&As[lr][lc] = av;
        *(float4*)&Bs[lr][lc] = bv;
        __syncthreads();
        #pragma unroll
        for (int k = 0; k < 8; k++) {
            float a[8], b[8];
            *(float4*)(a)     = *(const float4*)&As[k][ty * 8];
            *(float4*)(a + 4) = *(const float4*)&As[k][ty * 8 + 4];
            *(float4*)(b)     = *(const float4*)&Bs[k][tx * 4];
            *(float4*)(b + 4) = *(const float4*)&Bs[k][tx * 4 + 64];
            #pragma unroll
            for (int i = 0; i < 8; i++)
                #pragma unroll
                for (int j = 0; j < 8; j++) acc[i][j] += a[i] * b[j];
        }
        __syncthreads();
    }
    #pragma unroll
    for (int i = 0; i < 8; i++) {
        int gi = by * 128 + ty * 8 + i;
        float nai = na[gi];
        #pragma unroll
        for (int j = 0; j < 8; j++) {
            int gj = bx * 128 + (j < 4 ? tx * 4 + j : 64 + tx * 4 + j - 4);
            float v = expf(acc[i][j] / (nai * nb[gj] + 1e-6f) - 1.f);
            if (isYY && gi == gj) v += sigmaDiag;
            Cm[(size_t)gi * NPT + gj] = v;
        }
    }
}

// ---------------- unified double-buffered GEMM (conflict-free B frag) -------
// transB=0: op(B)=B^T (B row-major N x K); transB=1: op(B)=B (K x N).
// C = (beta ? C : 0) + alpha * A * op(B).
// ktri: 0 none; 1 kHi=(bx+1)*128; 2 kLo=bx*128; 3 kHi=(by+1)*128.
// z = batch*nodes + node; batch strides sAb.., node strides sAn..
// kSplit>0 (NT only): bx = k-chunk; C at column-chunk offset bx*NPT*128.
__global__ void __launch_bounds__(256) gemmx(const float* __restrict__ A,
        const float* __restrict__ B, float* __restrict__ Cm,
        int K, int lda, int ldb, int ldc,
        long long sAb, long long sBb, long long sCb,
        long long sAn, long long sBn, long long sCn,
        int nodes, int transB, float alpha, int beta,
        int ktri, int triSkip, int kSplit) {
    int bx = blockIdx.x, by = blockIdx.y, bz = blockIdx.z;
    if (triSkip && bx > by) return;
    int batch = bz / nodes, node = bz - batch * nodes;
    A  += (size_t)batch * sAb + (size_t)node * sAn;
    B  += (size_t)batch * sBb + (size_t)node * sBn;
    Cm += (size_t)batch * sCb + (size_t)node * sCn;

    int kLo = 0, kHi = K;
    if (ktri == 1)      { int h = (bx + 1) * 128; kHi = h < K ? h : K; }
    else if (ktri == 2) { kLo = bx * 128; }
    else if (ktri == 3) { int h = (by + 1) * 128; kHi = h < K ? h : K; }

    float* Cb;
    const float* Bb;
    if (kSplit) {
        kLo = bx * kSplit; kHi = kLo + kSplit;
        Cb = Cm + (size_t)bx * NPT * 128 + (size_t)(by * 128) * ldc;
        Bb = B;
    } else {
        Cb = Cm + (size_t)(by * 128) * ldc + bx * 128;
        Bb = transB ? (B + bx * 128) : (B + (size_t)(bx * 128) * ldb);
    }
    const float* Ab = A + (size_t)(by * 128) * lda;

    __shared__ float As[2][8][128], Bs[2][8][128];
    int tid = threadIdx.x;
    int tx = tid & 15, ty = tid >> 4;
    int lr = tid >> 1, lc = (tid & 1) << 2;      // NT staging (row, k-off)
    int lrB = tid >> 5, lcB = (tid & 31) << 2;   // NN staging (k-row, col)

    float acc[8][8];
    #pragma unroll
    for (int i = 0; i < 8; i++)
        #pragma unroll
        for (int j = 0; j < 8; j++) acc[i][j] = 0.f;

    int nk = (kHi - kLo) >> 3;
    float4 ra, rb;
    ra = *(const float4*)(Ab + (size_t)lr * lda + kLo + lc);
    if (transB == 0) rb = *(const float4*)(Bb + (size_t)lr * ldb + kLo + lc);
    else             rb = *(const float4*)(Bb + (size_t)(kLo + lrB) * ldb + lcB);
    As[0][lc + 0][lr] = ra.x; As[0][lc + 1][lr] = ra.y;
    As[0][lc + 2][lr] = ra.z; As[0][lc + 3][lr] = ra.w;
    if (transB == 0) {
        Bs[0][lc + 0][lr] = rb.x; Bs[0][lc + 1][lr] = rb.y;
        Bs[0][lc + 2][lr] = rb.z; Bs[0][lc + 3][lr] = rb.w;
    } else {
        *(float4*)&Bs[0][lrB][lcB] = rb;
    }
    __syncthreads();
    for (int s = 0; s < nk; s++) {
        int cur = s & 1;
        if (s + 1 < nk) {
            int kn = kLo + (s + 1) * 8;
            ra = *(const float4*)(Ab + (size_t)lr * lda + kn + lc);
            if (transB == 0) rb = *(const float4*)(Bb + (size_t)lr * ldb + kn + lc);
            else             rb = *(const float4*)(Bb + (size_t)(kn + lrB) * ldb + lcB);
        }
        #pragma unroll
        for (int k = 0; k < 8; k++) {
            float a[8], b[8];
            *(float4*)(a)     = *(const float4*)&As[cur][k][ty * 8];
            *(float4*)(a + 4) = *(const float4*)&As[cur][k][ty * 8 + 4];
            *(float4*)(b)     = *(const float4*)&Bs[cur][k][tx * 4];
            *(float4*)(b + 4) = *(const float4*)&Bs[cur][k][tx * 4 + 64];
            #pragma unroll
            for (int i = 0; i < 8; i++)
                #pragma unroll
                for (int j = 0; j < 8; j++) acc[i][j] += a[i] * b[j];
        }
        if (s + 1 < nk) {
            int nxt = cur ^ 1;
            As[nxt][lc + 0][lr] = ra.x; As[nxt][lc + 1][lr] = ra.y;
            As[nxt][lc + 2][lr] = ra.z; As[nxt][lc + 3][lr] = ra.w;
            if (transB == 0) {
                Bs[nxt][lc + 0][lr] = rb.x; Bs[nxt][lc + 1][lr] = rb.y;
                Bs[nxt][lc + 2][lr] = rb.z; Bs[nxt][lc + 3][lr] = rb.w;
            } else {
                *(float4*)&Bs[nxt][lrB][lcB] = rb;
            }
        }
        __syncthreads();
    }
    #pragma unroll
    for (int i = 0; i < 8; i++) {
        float* crow = Cb + (size_t)(ty * 8 + i) * ldc;
        float4* cp0 = (float4*)(crow + tx * 4);
        float4* cp1 = (float4*)(crow + tx * 4 + 64);
        float4 v0, v1;
        v0.x = alpha * acc[i][0]; v0.y = alpha * acc[i][1];
        v0.z = alpha * acc[i][2]; v0.w = alpha * acc[i][3];
        v1.x = alpha * acc[i][4]; v1.y = alpha * acc[i][5];
        v1.z = alpha * acc[i][6]; v1.w = alpha * acc[i][7];
        if (beta) {
            float4 o0 = *cp0, o1 = *cp1;
            v0.x += o0.x; v0.y += o0.y; v0.z += o0.z; v0.w += o0.w;
            v1.x += o1.x; v1.y += o1.y; v1.z += o1.z; v1.w += o1.w;
        }
        *cp0 = v0; *cp1 = v1;
    }
}

// ---------------- 256-thread diag Cholesky + blocked triangular inverse -----
// grid.x = batch. L diag block in/out; L^{-1} -> LI diag block (both lda NPT).
__global__ void __launch_bounds__(256) potf2_inv(float* __restrict__ Lbase,
        float* __restrict__ LIbase, int kblk) {
    int b = blockIdx.x;
    size_t off = (size_t)kblk * 128 * (NPT + 1);
    float* Ablk  = Lbase  + (size_t)b * LNN + off;
    float* IvBlk = LIbase + (size_t)b * LNN + off;
    extern __shared__ float sm[];
    float* As = sm;                   // 128 x 129
    float* Iv = sm + 128 * 129;       // 128 x 128
    float* W  = sm + 128 * 129 + 128 * 128;   // 16 x 112
    int tid = threadIdx.x;
    for (int idx = tid; idx < 128 * 128; idx += 256) {
        int r = idx >> 7, c = idx & 127;
        As[r * 129 + c] = Ablk[(size_t)r * NPT + c];
        Iv[idx] = 0.f;
    }
    __syncthreads();
    // panel-blocked right-looking Cholesky, PW=16
    for (int p0 = 0; p0 < 128; p0 += 16) {
        for (int j = p0; j < p0 + 16; j++) {
            if (tid == 0) As[j * 129 + j] = sqrtf(As[j * 129 + j]);
            __syncthreads();
            float d = As[j * 129 + j];
            if (tid > j && tid < 128) As[tid * 129 + j] /= d;
            __syncthreads();
            if (tid > j && tid < 128) {
                float lj = As[tid * 129 + j];
                for (int m = j + 1; m < p0 + 16; m++)
                    As[tid * 129 + m] -= lj * As[m * 129 + j];
            }
            __syncthreads();
        }
        int m = tid & 127, half = tid >> 7;
        if (m >= p0 + 16) {
            float pj[16];
            #pragma unroll
            for (int jj = 0; jj < 16; jj++) pj[jj] = As[m * 129 + p0 + jj];
            for (int t = m + half; t < 128; t += 2) {
                float a = 0.f;
                #pragma unroll
                for (int jj = 0; jj < 16; jj++) a += As[t * 129 + p0 + jj] * pj[jj];
                As[t * 129 + m] -= a;
            }
        }
        __syncthreads();
    }
    // 16x16 diag block inverses (threads 0..127)
    if (tid < 128) {
        int db = tid >> 4, c = tid & 15, base = db * 16;
        for (int t = 0; t < 16; t++) {
            float v;
            if (t < c) v = 0.f;
            else if (t == c) v = 1.f / As[(base + t) * 129 + base + c];
            else {
                float s = 0.f;
                for (int m2 = c; m2 < t; m2++)
                    s += As[(base + t) * 129 + base + m2] * Iv[(base + m2) * 128 + base + c];
                v = -s / As[(base + t) * 129 + base + t];
            }
            Iv[(base + t) * 128 + base + c] = v;
        }
    }
    __syncthreads();
    // blocked forward substitution for the full 128x128 inverse
    for (int tb = 1; tb < 8; tb++) {
        int R = tb * 16, ncol = tb * 16, total = 16 * ncol;
        for (int idx = tid; idx < total; idx += 256) {
            int s = idx / ncol, c2 = idx % ncol;
            float a = 0.f;
            for (int m2 = c2; m2 < R; m2++)
                a += As[(R + s) * 129 + m2] * Iv[m2 * 128 + c2];
            W[s * 112 + c2] = a;
        }
        __syncthreads();
        for (int idx = tid; idx < total; idx += 256) {
            int r = idx / ncol, c2 = idx % ncol;
            float a = 0.f;
            for (int s = 0; s <= r; s++)
                a += Iv[(R + r) * 128 + R + s] * W[s * 112 + c2];
            Iv[(R + r) * 128 + c2] = -a;
        }
        __syncthreads();
    }
    for (int idx = tid; idx < 128 * 128; idx += 256) {
        int r = idx >> 7, c = idx & 127;
        Ablk[(size_t)r * NPT + c] = As[r * 129 + c];
        IvBlk[(size_t)r * NPT + c] = Iv[idx];
    }
}

// ---------------- mu reduce ----------------
__global__ void reduce_mu(const float* __restrict__ MUP, float* __restrict__ out) {
    int b = blockIdx.z;
    int idx = blockIdx.x * blockDim.x + threadIdx.x;   // 64*4096
    int dch = idx >> 12, p = idx & 4095;
    const float* base = MUP + (size_t)b * 8 * NPT * 128 + (size_t)p * 128 + dch;
    float s = 0.f;
    #pragma unroll
    for (int c = 0; c < 8; c++) s += base[(size_t)c * NPT * 128];
    out[(size_t)b * 89 * NPT + (size_t)dch * NPT + p] = s;
}

// ---------------- local covariance, 4 p's per block --------------------------
// grid (1024, 1, 2). Stages 4 consecutive p-rows of X2 and XF in smem; each
// of the <=40 distinct neighbor q-rows is streamed from global ONCE per block.
__global__ void __launch_bounds__(256) local4_k(const float* __restrict__ Xg,
        const float* __restrict__ XFg, const float* __restrict__ xng,
        float* __restrict__ out) {
    int b = blockIdx.z;
    const float* X  = Xg  + (size_t)b * XNN;
    const float* XF = XFg + (size_t)b * NPT * 512;
    const float* xn = xng + (size_t)b * NPT;
    float* outb = out + (size_t)b * 89 * NPT;

    __shared__ __align__(16) float sXp[4][4096];   // 64 KB
    __shared__ __align__(16) float sXf[4][512];    // 8 KB
    __shared__ float sRed[8][8];

    int tid = threadIdx.x;
    int p0 = blockIdx.x * 4;
    int i0 = p0 >> 6, j0 = p0 & 63;

    // zero all 25 channels for the 4 p's (overwritten below where valid)
    for (int idx = tid; idx < 100; idx += 256) {
        int pp = idx >> 5; // 0..3 (idx/32), idx%32 < 25 guard:
        int kk = idx & 31;
        if (pp < 4 && kk < 25)
            outb[(size_t)(64 + kk) * NPT + p0 + pp] = 0.f;
    }
    // stage p rows
    #pragma unroll
    for (int pp = 0; pp < 4; pp++) {
        const float4* src = (const float4*)(X + (size_t)(p0 + pp) * NPT);
        for (int t = tid; t < 1024; t += 256) ((float4*)sXp[pp])[t] = src[t];
        const float4* sf = (const float4*)(XF + (size_t)(p0 + pp) * 512);
        if (tid < 128) ((float4*)sXf[pp])[tid] = sf[tid];
    }
    __syncthreads();

    float nxp[4];
    #pragma unroll
    for (int pp = 0; pp < 4; pp++) nxp[pp] = xn[p0 + pp];

    int warp = tid >> 5, lane = tid & 31;

    for (int dr = -2; dr <= 2; dr++) {
        int qi = i0 + dr;
        if (qi < 0 || qi >= 64) continue;
        for (int dq = -2; dq <= 5; dq++) {
            int qj = j0 + dq;
            if (qj < 0 || qj >= 64) continue;
            int q = qi * 64 + qj;

            // dots vs 4 staged p rows
            float s[4] = {0.f, 0.f, 0.f, 0.f};
            const float4* Xq4 = (const float4*)(X + (size_t)q * NPT);
            for (int t = tid; t < 1024; t += 256) {
                float4 bq = Xq4[t];
                #pragma unroll
                for (int pp = 0; pp < 4; pp++) {
                    float4 a = ((const float4*)sXp[pp])[t];
                    s[pp] += a.x * bq.x + a.y * bq.y + a.z * bq.z + a.w * bq.w;
                }
            }
            float s2[4] = {0.f, 0.f, 0.f, 0.f};
            if (tid < 128) {
                float4 bq = ((const float4*)(XF + (size_t)q * 512))[tid];
                #pragma unroll
                for (int pp = 0; pp < 4; pp++) {
                    float4 a = ((const float4*)sXf[pp])[tid];
                    s2[pp] += a.x * bq.x + a.y * bq.y + a.z * bq.z + a.w * bq.w;
                }
            }
            // reduce 8 values
            #pragma unroll
            for (int o = 16; o; o >>= 1) {
                #pragma unroll
                for (int pp = 0; pp < 4; pp++) {
                    s[pp]  += __shfl_down_sync(0xffffffffu, s[pp],  o);
                    s2[pp] += __shfl_down_sync(0xffffffffu, s2[pp], o);
                }
            }
            if (lane == 0) {
                #pragma unroll
                for (int pp = 0; pp < 4; pp++) {
                    sRed[warp][pp] = s[pp];
                    sRed[warp][4 + pp] = s2[pp];
                }
            }
            __syncthreads();
            if (tid < 4) {
                int pp = tid;
                int dc = qj - (j0 + pp);
                if (dc >= -2 && dc <= 2) {
                    float ts = 0.f, ts2 = 0.f;
                    #pragma unroll
                    for (int w = 0; w < 8; w++) { ts += sRed[w][pp]; ts2 += sRed[w][4 + pp]; }
                    int kk = (dr + 2) * 5 + (dc + 2);
                    float kxx = expf(ts2 / (nxp[pp] * xn[q] + 1e-6f) - 1.f);
                    outb[(size_t)(64 + kk) * NPT + p0 + pp] = kxx - ts;
                }
            }
            __syncthreads();
        }
    }
}

// ---------------------------------------------------------------------------
extern "C" void kernel_launch(void* const* d_in, const int* in_sizes, int n_in,
                              void* d_out, int out_size) {
    const float* x  = (const float*)d_in[0];
    const float* y  = (const float*)d_in[1];
    const float* pw = (const float*)d_in[2];
    const float* pb = (const float*)d_in[3];
    float* out = (float*)d_out;
    (void)in_sizes; (void)n_in; (void)out_size;

    float *pL, *pLI, *pX, *pX2, *pT, *pXF, *pMUP, *pxn, *pyn;
    cudaGetSymbolAddress((void**)&pL,   g_L);
    cudaGetSymbolAddress((void**)&pLI,  g_LI);
    cudaGetSymbolAddress((void**)&pX,   g_X);
    cudaGetSymbolAddress((void**)&pX2,  g_X2);
    cudaGetSymbolAddress((void**)&pT,   g_T);
    cudaGetSymbolAddress((void**)&pXF,  g_XF);
    cudaGetSymbolAddress((void**)&pMUP, g_MUP);
    cudaGetSymbolAddress((void**)&pxn,  g_xn);
    cudaGetSymbolAddress((void**)&pyn,  g_yn);

    const int PSMEM = (128 * 129 + 128 * 128 + 16 * 112) * 4;
    cudaFuncSetAttribute(potf2_inv, cudaFuncAttributeMaxDynamicSharedMemorySize, PSMEM);

    // ---- prep (both batches per launch) ----
    norms2_k<<<dim3(16, 2, 2), 256>>>(x, y, pxn, pyn);
    transpose_k<<<dim3(128, 16, 2), dim3(32, 8)>>>(x, pXF);
    gram2<<<dim3(32, 64, 2), 256>>>(x, y, pL, pX, pxn, pyn, 0.1f);
    features_k<<<dim3(1024, 1, 2), 256>>>(pw, pb, pX);
    // note: pad rows (4160..4223) of g_X stay zero invariantly (.bss, and all
    // updates preserve zero), so no zeroing launch is needed.

    // ---- blocked Cholesky (NB=128, z-batched); iL128 -> LI diag blocks ----
    for (int k = 0; k < NBLK; k++) {
        potf2_inv<<<2, 256, PSMEM>>>(pL, pLI, k);
        if (k < NBLK - 1) {
            int rem = NBLK - 1 - k;
            size_t panOff  = (size_t)(k + 1) * 128 * NPT + (size_t)k * 128;
            size_t diagOff = (size_t)k * 128 * (NPT + 1);
            gemmx<<<dim3(1, rem, 2), 256>>>(pL + panOff, pLI + diagOff, pL + panOff,
                    128, NPT, NPT, NPT, LNN, LNN, LNN, 0, 0, 0,
                    1, /*NT*/0, 1.f, 0, 0, 0, 0);
            size_t trailOff = (size_t)(k + 1) * 128 * (NPT + 1);
            gemmx<<<dim3(rem, rem, 2), 256>>>(pL + panOff, pL + panOff, pL + trailOff,
                    128, NPT, NPT, NPT, LNN, LNN, LNN, 0, 0, 0,
                    1, /*NT*/0, -1.f, 1, 0, 1, 0);
        }
    }

    // ---- build iL512 of each 512x512 diagonal super-block (4 launches) ----
    {
        long long sN = (long long)256 * (NPT + 1);
        long long tN = 128 * 128, tB = 16 * tN;
        gemmx<<<dim3(1, 1, 32), 256>>>(
                pL + (size_t)128 * NPT, pLI, pT,
                128, NPT, NPT, 128, LNN, LNN, tB, sN, sN, tN,
                16, /*NN*/1, 1.f, 0, 2, 0, 0);
        gemmx<<<dim3(1, 1, 32), 256>>>(
                pLI + (size_t)128 * NPT + 128, pT, pLI + (size_t)128 * NPT,
                128, NPT, 128, NPT, LNN, tB, LNN, sN, tN, sN,
                16, /*NN*/1, -1.f, 0, 3, 0, 0);
        long long sN2 = (long long)512 * (NPT + 1);
        long long tN2 = 256 * 256, tB2 = 8 * tN2;
        gemmx<<<dim3(2, 2, 16), 256>>>(
                pL + (size_t)256 * NPT, pLI, pT,
                256, NPT, NPT, 256, LNN, LNN, tB2, sN2, sN2, tN2,
                8, /*NN*/1, 1.f, 0, 2, 0, 0);
        gemmx<<<dim3(2, 2, 16), 256>>>(
                pLI + (size_t)256 * NPT + 256, pT, pLI + (size_t)256 * NPT,
                256, NPT, 256, NPT, LNN, tB2, LNN, sN2, tN2, sN2,
                8, /*NN*/1, -1.f, 0, 3, 0, 0);
    }

    // ---- right-TRSM in 8 super-steps of 512 columns ----
    for (int J = 0; J < 8; J++) {
        size_t col = (size_t)J * 512;
        if (J > 0) {
            gemmx<<<dim3(4, MROWS / 128, 2), 256>>>(
                    pX2, pL + col * NPT, pX + col,
                    J * 512, NPT, NPT, NPT, XNN, LNN, XNN, 0, 0, 0,
                    1, /*NT*/0, -1.f, 1, 0, 0, 0);
        }
        gemmx<<<dim3(4, MROWS / 128, 2), 256>>>(
                pX + col, pLI + col * (NPT + 1), pX2 + col,
                512, NPT, NPT, NPT, XNN, LNN, XNN, 0, 0, 0,
                1, /*NT*/0, 1.f, 0, 1, 0, 0);
    }

    // ---- mu: split-K (8 x 512), then reduce ----
    gemmx<<<dim3(8, 32, 2), 256>>>(pX2, pX2 + LNN, pMUP,
            NPT, NPT, NPT, 128, XNN, XNN, (long long)8 * NPT * 128, 0, 0, 0,
            1, /*NT*/0, 1.f, 0, 0, 0, 512);
    reduce_mu<<<dim3(1024, 1, 2), 256>>>(pMUP, out);

    // ---- local covariance channels (4 p's per block) ----
    local4_k<<<dim3(1024, 1, 2), 256>>>(pX2, pXF, pxn, out);
}

// round 17
// speedup vs baseline: 1.0110x; 1.0110x over previous
#include <cuda_runtime.h>
#include <math.h>

// ---------------------------------------------------------------------------
// b=2, c=512, h=w=64 -> n=4096 points, d=64 features, 5x5 local cov.
// out[b] = concat(mu (64 ch), local cov (25 ch)) -> (2, 89, 64, 64) fp32.
//
//   K_yy+sigma I = L L^T     (blocked Cholesky NB=128, z-batched)
//   iL512_J = inverse of each 512x512 diagonal super-block of L
//            (recursive-doubling merges, z-batched over nodes: 4 launches)
//   X (in g_X2) = [K_xy ; ff^T] L^{-T} via 8 super-steps:
//       J>0: X[:,J] -= X2[:,<J] * L[J,<J]^T    (one K=J*512 GEMM)
//       X2[:,J] = X[:,J] * iL512_J^T           (one K-clipped GEMM)
//   mu = X2(0:4096) @ X2(4096:4160)^T          (split-K)
//   cov[p,q] = K_xx[p,q] - X2[p,:].X2[q,:]     (5x5 neighbors only)
//
// All GEMMs fp32 (cond(K_yy+sigma I) ~ 1.5e4 excludes <=2-limb tensor paths).
// GEMM inner loop: A-fragment warp-broadcast; B-fragment split into two
// conflict-free float4s at cols tx*4 and tx*4+64 (no smem bank conflicts).
// Launch order puts step-0 SYRK at launch index 6 so ncu (-s 5 -c 1)
// profiles the representative big GEMM.
// ---------------------------------------------------------------------------

#define NPT   4096
#define MROWS 4224
#define NBLK  32
#define LNN   ((size_t)NPT * NPT)
#define XNN   ((size_t)MROWS * NPT)

__device__ float g_L  [2 * LNN];             // K_yy -> L (lower)
__device__ float g_LI [2 * LNN];             // iL128 diags + merge panels (lower)
__device__ float g_X  [2 * XNN];             // [K_xy ; ff^T ; 0], working
__device__ float g_X2 [2 * XNN];             // solved columns
__device__ float g_T  [2 * (size_t)1024 * 1024];  // tree temps
__device__ float g_XF [2 * (size_t)NPT * 512];
__device__ float g_MUP[2 * 8 * (size_t)NPT * 128];
__device__ float g_xn [2 * NPT];
__device__ float g_yn [2 * NPT];

// ---------------- prep kernels (z = batch) ----------------
__global__ void norms2_k(const float* __restrict__ x, const float* __restrict__ y,
                         float* __restrict__ xn, float* __restrict__ yn) {
    int b = blockIdx.z, sel = blockIdx.y;
    const float* v = (sel ? y : x) + (size_t)b * 512 * NPT;
    float* o = (sel ? yn : xn) + (size_t)b * NPT;
    int p = blockIdx.x * blockDim.x + threadIdx.x;
    float s = 0.f;
    for (int ch = 0; ch < 512; ch++) { float t = v[(size_t)ch * NPT + p]; s += t * t; }
    o[p] = sqrtf(s);
}

__global__ void transpose_k(const float* __restrict__ x, float* __restrict__ of) {
    int b = blockIdx.z;
    const float* v = x + (size_t)b * 512 * NPT;
    float* o = of + (size_t)b * NPT * 512;
    __shared__ float t[32][33];
    int pb = blockIdx.x * 32, cb = blockIdx.y * 32;
    for (int yy = threadIdx.y; yy < 32; yy += 8)
        t[yy][threadIdx.x] = v[(size_t)(cb + yy) * NPT + pb + threadIdx.x];
    __syncthreads();
    for (int yy = threadIdx.y; yy < 32; yy += 8)
        o[(size_t)(pb + yy) * 512 + cb + threadIdx.x] = t[threadIdx.x][yy];
}

__global__ void features_k(const float* __restrict__ pw, const float* __restrict__ pb,
                           float* __restrict__ X) {
    int b = blockIdx.z;
    int idx = blockIdx.x * blockDim.x + threadIdx.x;   // 4096*64
    int q = idx & 4095, dch = idx >> 12;
    float gx = (2.f * (float)(q & 63) + 1.f) * (1.f / 64.f) - 1.f;
    float gy = (2.f * (float)(q >> 6) + 1.f) * (1.f / 64.f) - 1.f;
    float ph = pw[dch * 2 + 0] * gx + pw[dch * 2 + 1] * gy + pb[dch];
    X[(size_t)b * XNN + LNN + (size_t)dch * NPT + q] = cosf(25.132741228718345f * ph);
}

// ---------------- fused Gram: K_yy (lower,+sigma) and K_xy in one launch ----
// grid (32, 64, 2): by<32 -> C=L, A=y, lower-only; by>=32 -> C=X, A=x, full.
__global__ void __launch_bounds__(256) gram2(const float* __restrict__ x,
        const float* __restrict__ y, float* __restrict__ Lout, float* __restrict__ Xout,
        const float* __restrict__ xn, const float* __restrict__ yn, float sigmaDiag) {
    int bx = blockIdx.x, byr = blockIdx.y, bz = blockIdx.z;
    int isYY = (byr < 32);
    int by = isYY ? byr : byr - 32;
    if (isYY && bx > by) return;
    const float* A = (isYY ? y : x) + (size_t)bz * 512 * NPT;
    const float* B = y + (size_t)bz * 512 * NPT;
    float* Cm = isYY ? (Lout + (size_t)bz * LNN) : (Xout + (size_t)bz * XNN);
    const float* na = (isYY ? yn : xn) + (size_t)bz * NPT;
    const float* nb = yn + (size_t)bz * NPT;
    __shared__ float As[8][128], Bs[8][128];
    int tid = threadIdx.x;
    int tx = tid & 15, ty = tid >> 4;
    const float* Ab = A + by * 128;
    const float* Bb = B + bx * 128;
    float acc[8][8];
    #pragma unroll
    for (int i = 0; i < 8; i++)
        #pragma unroll
        for (int j = 0; j < 8; j++) acc[i][j] = 0.f;
    int lr = tid >> 5;
    int lc = (tid & 31) << 2;
    for (int k0 = 0; k0 < 512; k0 += 8) {
        float4 av = *(const float4*)(Ab + (size_t)(k0 + lr) * NPT + lc);
        float4 bv = *(const float4*)(Bb + (size_t)(k0 + lr) * NPT + lc);
        *(float4*)&As[lr][lc] = av;
        *(float4*)&Bs[lr][lc] = bv;
        __syncthreads();
        #pragma unroll
        for (int k = 0; k < 8; k++) {
            float a[8], b[8];
            *(float4*)(a)     = *(const float4*)&As[k][ty * 8];
            *(float4*)(a + 4) = *(const float4*)&As[k][ty * 8 + 4];
            *(float4*)(b)     = *(const float4*)&Bs[k][tx * 4];
            *(float4*)(b + 4) = *(const float4*)&Bs[k][tx * 4 + 64];
            #pragma unroll
            for (int i = 0; i < 8; i++)
                #pragma unroll
                for (int j = 0; j < 8; j++) acc[i][j] += a[i] * b[j];
        }
        __syncthreads();
    }
    #pragma unroll
    for (int i = 0; i < 8; i++) {
        int gi = by * 128 + ty * 8 + i;
        float nai = na[gi];
        #pragma unroll
        for (int j = 0; j < 8; j++) {
            int gj = bx * 128 + (j < 4 ? tx * 4 + j : 64 + tx * 4 + j - 4);
            float v = expf(acc[i][j] / (nai * nb[gj] + 1e-6f) - 1.f);
            if (isYY && gi == gj) v += sigmaDiag;
            Cm[(size_t)gi * NPT + gj] = v;
        }
    }
}

// ---------------- unified double-buffered GEMM (conflict-free B frag) -------
// transB=0: op(B)=B^T (B row-major N x K); transB=1: op(B)=B (K x N).
// C = (beta ? C : 0) + alpha * A * op(B).
// ktri: 0 none; 1 kHi=(bx+1)*128; 2 kLo=bx*128; 3 kHi=(by+1)*128.
// z = batch*nodes + node; batch strides sAb.., node strides sAn..
// kSplit>0 (NT only): bx = k-chunk; C at column-chunk offset bx*NPT*128.
__global__ void __launch_bounds__(256) gemmx(const float* __restrict__ A,
        const float* __restrict__ B, float* __restrict__ Cm,
        int K, int lda, int ldb, int ldc,
        long long sAb, long long sBb, long long sCb,
        long long sAn, long long sBn, long long sCn,
        int nodes, int transB, float alpha, int beta,
        int ktri, int triSkip, int kSplit) {
    int bx = blockIdx.x, by = blockIdx.y, bz = blockIdx.z;
    if (triSkip && bx > by) return;
    int batch = bz / nodes, node = bz - batch * nodes;
    A  += (size_t)batch * sAb + (size_t)node * sAn;
    B  += (size_t)batch * sBb + (size_t)node * sBn;
    Cm += (size_t)batch * sCb + (size_t)node * sCn;

    int kLo = 0, kHi = K;
    if (ktri == 1)      { int h = (bx + 1) * 128; kHi = h < K ? h : K; }
    else if (ktri == 2) { kLo = bx * 128; }
    else if (ktri == 3) { int h = (by + 1) * 128; kHi = h < K ? h : K; }

    float* Cb;
    const float* Bb;
    if (kSplit) {
        kLo = bx * kSplit; kHi = kLo + kSplit;
        Cb = Cm + (size_t)bx * NPT * 128 + (size_t)(by * 128) * ldc;
        Bb = B;
    } else {
        Cb = Cm + (size_t)(by * 128) * ldc + bx * 128;
        Bb = transB ? (B + bx * 128) : (B + (size_t)(bx * 128) * ldb);
    }
    const float* Ab = A + (size_t)(by * 128) * lda;

    __shared__ float As[2][8][128], Bs[2][8][128];
    int tid = threadIdx.x;
    int tx = tid & 15, ty = tid >> 4;
    int lr = tid >> 1, lc = (tid & 1) << 2;      // NT staging (row, k-off)
    int lrB = tid >> 5, lcB = (tid & 31) << 2;   // NN staging (k-row, col)

    float acc[8][8];
    #pragma unroll
    for (int i = 0; i < 8; i++)
        #pragma unroll
        for (int j = 0; j < 8; j++) acc[i][j] = 0.f;

    int nk = (kHi - kLo) >> 3;
    float4 ra, rb;
    ra = *(const float4*)(Ab + (size_t)lr * lda + kLo + lc);
    if (transB == 0) rb = *(const float4*)(Bb + (size_t)lr * ldb + kLo + lc);
    else             rb = *(const float4*)(Bb + (size_t)(kLo + lrB) * ldb + lcB);
    As[0][lc + 0][lr] = ra.x; As[0][lc + 1][lr] = ra.y;
    As[0][lc + 2][lr] = ra.z; As[0][lc + 3][lr] = ra.w;
    if (transB == 0) {
        Bs[0][lc + 0][lr] = rb.x; Bs[0][lc + 1][lr] = rb.y;
        Bs[0][lc + 2][lr] = rb.z; Bs[0][lc + 3][lr] = rb.w;
    } else {
        *(float4*)&Bs[0][lrB][lcB] = rb;
    }
    __syncthreads();
    for (int s = 0; s < nk; s++) {
        int cur = s & 1;
        if (s + 1 < nk) {
            int kn = kLo + (s + 1) * 8;
            ra = *(const float4*)(Ab + (size_t)lr * lda + kn + lc);
            if (transB == 0) rb = *(const float4*)(Bb + (size_t)lr * ldb + kn + lc);
            else             rb = *(const float4*)(Bb + (size_t)(kn + lrB) * ldb + lcB);
        }
        #pragma unroll
        for (int k = 0; k < 8; k++) {
            float a[8], b[8];
            *(float4*)(a)     = *(const float4*)&As[cur][k][ty * 8];
            *(float4*)(a + 4) = *(const float4*)&As[cur][k][ty * 8 + 4];
            *(float4*)(b)     = *(const float4*)&Bs[cur][k][tx * 4];
            *(float4*)(b + 4) = *(const float4*)&Bs[cur][k][tx * 4 + 64];
            #pragma unroll
            for (int i = 0; i < 8; i++)
                #pragma unroll
                for (int j = 0; j < 8; j++) acc[i][j] += a[i] * b[j];
        }
        if (s + 1 < nk) {
            int nxt = cur ^ 1;
            As[nxt][lc + 0][lr] = ra.x; As[nxt][lc + 1][lr] = ra.y;
            As[nxt][lc + 2][lr] = ra.z; As[nxt][lc + 3][lr] = ra.w;
            if (transB == 0) {
                Bs[nxt][lc + 0][lr] = rb.x; Bs[nxt][lc + 1][lr] = rb.y;
                Bs[nxt][lc + 2][lr] = rb.z; Bs[nxt][lc + 3][lr] = rb.w;
            } else {
                *(float4*)&Bs[nxt][lrB][lcB] = rb;
            }
        }
        __syncthreads();
    }
    #pragma unroll
    for (int i = 0; i < 8; i++) {
        float* crow = Cb + (size_t)(ty * 8 + i) * ldc;
        float4* cp0 = (float4*)(crow + tx * 4);
        float4* cp1 = (float4*)(crow + tx * 4 + 64);
        float4 v0, v1;
        v0.x = alpha * acc[i][0]; v0.y = alpha * acc[i][1];
        v0.z = alpha * acc[i][2]; v0.w = alpha * acc[i][3];
        v1.x = alpha * acc[i][4]; v1.y = alpha * acc[i][5];
        v1.z = alpha * acc[i][6]; v1.w = alpha * acc[i][7];
        if (beta) {
            float4 o0 = *cp0, o1 = *cp1;
            v0.x += o0.x; v0.y += o0.y; v0.z += o0.z; v0.w += o0.w;
            v1.x += o1.x; v1.y += o1.y; v1.z += o1.z; v1.w += o1.w;
        }
        *cp0 = v0; *cp1 = v1;
    }
}

// ---------------- 256-thread diag Cholesky + blocked triangular inverse -----
// grid.x = batch. L diag block in/out; L^{-1} -> LI diag block (both lda NPT).
__global__ void __launch_bounds__(256) potf2_inv(float* __restrict__ Lbase,
        float* __restrict__ LIbase, int kblk) {
    int b = blockIdx.x;
    size_t off = (size_t)kblk * 128 * (NPT + 1);
    float* Ablk  = Lbase  + (size_t)b * LNN + off;
    float* IvBlk = LIbase + (size_t)b * LNN + off;
    extern __shared__ float sm[];
    float* As = sm;                   // 128 x 129
    float* Iv = sm + 128 * 129;       // 128 x 128
    float* W  = sm + 128 * 129 + 128 * 128;   // 16 x 112
    int tid = threadIdx.x;
    for (int idx = tid; idx < 128 * 128; idx += 256) {
        int r = idx >> 7, c = idx & 127;
        As[r * 129 + c] = Ablk[(size_t)r * NPT + c];
        Iv[idx] = 0.f;
    }
    __syncthreads();
    // panel-blocked right-looking Cholesky, PW=16
    for (int p0 = 0; p0 < 128; p0 += 16) {
        for (int j = p0; j < p0 + 16; j++) {
            if (tid == 0) As[j * 129 + j] = sqrtf(As[j * 129 + j]);
            __syncthreads();
            float d = As[j * 129 + j];
            if (tid > j && tid < 128) As[tid * 129 + j] /= d;
            __syncthreads();
            if (tid > j && tid < 128) {
                float lj = As[tid * 129 + j];
                for (int m = j + 1; m < p0 + 16; m++)
                    As[tid * 129 + m] -= lj * As[m * 129 + j];
            }
            __syncthreads();
        }
        int m = tid & 127, half = tid >> 7;
        if (m >= p0 + 16) {
            float pj[16];
            #pragma unroll
            for (int jj = 0; jj < 16; jj++) pj[jj] = As[m * 129 + p0 + jj];
            for (int t = m + half; t < 128; t += 2) {
                float a = 0.f;
                #pragma unroll
                for (int jj = 0; jj < 16; jj++) a += As[t * 129 + p0 + jj] * pj[jj];
                As[t * 129 + m] -= a;
            }
        }
        __syncthreads();
    }
    // 16x16 diag block inverses (threads 0..127)
    if (tid < 128) {
        int db = tid >> 4, c = tid & 15, base = db * 16;
        for (int t = 0; t < 16; t++) {
            float v;
            if (t < c) v = 0.f;
            else if (t == c) v = 1.f / As[(base + t) * 129 + base + c];
            else {
                float s = 0.f;
                for (int m2 = c; m2 < t; m2++)
                    s += As[(base + t) * 129 + base + m2] * Iv[(base + m2) * 128 + base + c];
                v = -s / As[(base + t) * 129 + base + t];
            }
            Iv[(base + t) * 128 + base + c] = v;
        }
    }
    __syncthreads();
    // blocked forward substitution for the full 128x128 inverse
    for (int tb = 1; tb < 8; tb++) {
        int R = tb * 16, ncol = tb * 16, total = 16 * ncol;
        for (int idx = tid; idx < total; idx += 256) {
            int s = idx / ncol, c2 = idx % ncol;
            float a = 0.f;
            for (int m2 = c2; m2 < R; m2++)
                a += As[(R + s) * 129 + m2] * Iv[m2 * 128 + c2];
            W[s * 112 + c2] = a;
        }
        __syncthreads();
        for (int idx = tid; idx < total; idx += 256) {
            int r = idx / ncol, c2 = idx % ncol;
            float a = 0.f;
            for (int s = 0; s <= r; s++)
                a += Iv[(R + r) * 128 + R + s] * W[s * 112 + c2];
            Iv[(R + r) * 128 + c2] = -a;
        }
        __syncthreads();
    }
    for (int idx = tid; idx < 128 * 128; idx += 256) {
        int r = idx >> 7, c = idx & 127;
        Ablk[(size_t)r * NPT + c] = As[r * 129 + c];
        IvBlk[(size_t)r * NPT + c] = Iv[idx];
    }
}

// ---------------- mu reduce ----------------
__global__ void reduce_mu(const float* __restrict__ MUP, float* __restrict__ out) {
    int b = blockIdx.z;
    int idx = blockIdx.x * blockDim.x + threadIdx.x;   // 64*4096
    int dch = idx >> 12, p = idx & 4095;
    const float* base = MUP + (size_t)b * 8 * NPT * 128 + (size_t)p * 128 + dch;
    float s = 0.f;
    #pragma unroll
    for (int c = 0; c < 8; c++) s += base[(size_t)c * NPT * 128];
    out[(size_t)b * 89 * NPT + (size_t)dch * NPT + p] = s;
}

// ---------------- local covariance + Kxx on 5x5 neighborhoods ----------------
__global__ void __launch_bounds__(256) local_k(const float* __restrict__ Xg,
        const float* __restrict__ XFg, const float* __restrict__ xng,
        float* __restrict__ out) {
    int b = blockIdx.z;
    const float* X  = Xg  + (size_t)b * XNN;
    const float* XF = XFg + (size_t)b * NPT * 512;
    const float* xn = xng + (size_t)b * NPT;
    float* outb = out + (size_t)b * 89 * NPT;
    __shared__ __align__(16) float sXp[4096];
    __shared__ __align__(16) float sXf[512];
    __shared__ float sRed[16];
    int p = blockIdx.x, tid = threadIdx.x;
    const float4* Xp4 = (const float4*)(X + (size_t)p * NPT);
    for (int t = tid; t < 1024; t += 256) ((float4*)sXp)[t] = Xp4[t];
    const float4* xf4 = (const float4*)(XF + (size_t)p * 512);
    if (tid < 128) ((float4*)sXf)[tid] = xf4[tid];
    __syncthreads();
    int i0 = p >> 6, j0 = p & 63;
    float nxp = xn[p];
    int warp = tid >> 5, lane = tid & 31;
    for (int kk = 0; kk < 25; kk++) {
        int dr = kk / 5 - 2, dc = kk % 5 - 2;
        int qi = i0 + dr, qj = j0 + dc;
        bool valid = (qi >= 0) & (qi < 64) & (qj >= 0) & (qj < 64);
        __syncthreads();
        if (!valid) {
            if (tid == 0) outb[(size_t)(64 + kk) * NPT + p] = 0.f;
            continue;
        }
        int q = qi * 64 + qj;
        const float4* Xq4 = (const float4*)(X + (size_t)q * NPT);
        float s = 0.f;
        for (int t = tid; t < 1024; t += 256) {
            float4 a = ((const float4*)sXp)[t];
            float4 bq = Xq4[t];
            s += a.x * bq.x + a.y * bq.y + a.z * bq.z + a.w * bq.w;
        }
        float s2 = 0.f;
        const float4* xq4 = (const float4*)(XF + (size_t)q * 512);
        if (tid < 128) {
            float4 a = ((const float4*)sXf)[tid];
            float4 bq = xq4[tid];
            s2 = a.x * bq.x + a.y * bq.y + a.z * bq.z + a.w * bq.w;
        }
        #pragma unroll
        for (int o = 16; o; o >>= 1) {
            s  += __shfl_down_sync(0xffffffffu, s,  o);
            s2 += __shfl_down_sync(0xffffffffu, s2, o);
        }
        if (lane == 0) { sRed[warp] = s; sRed[8 + warp] = s2; }
        __syncthreads();
        if (tid == 0) {
            float ts = 0.f, ts2 = 0.f;
            #pragma unroll
            for (int w = 0; w < 8; w++) { ts += sRed[w]; ts2 += sRed[8 + w]; }
            float kxx = expf(ts2 / (nxp * xn[q] + 1e-6f) - 1.f);
            outb[(size_t)(64 + kk) * NPT + p] = kxx - ts;
        }
    }
}

// ---------------------------------------------------------------------------
extern "C" void kernel_launch(void* const* d_in, const int* in_sizes, int n_in,
                              void* d_out, int out_size) {
    const float* x  = (const float*)d_in[0];
    const float* y  = (const float*)d_in[1];
    const float* pw = (const float*)d_in[2];
    const float* pb = (const float*)d_in[3];
    float* out = (float*)d_out;
    (void)in_sizes; (void)n_in; (void)out_size;

    float *pL, *pLI, *pX, *pX2, *pT, *pXF, *pMUP, *pxn, *pyn;
    cudaGetSymbolAddress((void**)&pL,   g_L);
    cudaGetSymbolAddress((void**)&pLI,  g_LI);
    cudaGetSymbolAddress((void**)&pX,   g_X);
    cudaGetSymbolAddress((void**)&pX2,  g_X2);
    cudaGetSymbolAddress((void**)&pT,   g_T);
    cudaGetSymbolAddress((void**)&pXF,  g_XF);
    cudaGetSymbolAddress((void**)&pMUP, g_MUP);
    cudaGetSymbolAddress((void**)&pxn,  g_xn);
    cudaGetSymbolAddress((void**)&pyn,  g_yn);

    const int PSMEM = (128 * 129 + 128 * 128 + 16 * 112) * 4;
    cudaFuncSetAttribute(potf2_inv, cudaFuncAttributeMaxDynamicSharedMemorySize, PSMEM);

    // ---- prep; chol step 0 placed so its SYRK is launch #6 for ncu ----
    norms2_k<<<dim3(16, 2, 2), 256>>>(x, y, pxn, pyn);                 // 1
    transpose_k<<<dim3(128, 16, 2), dim3(32, 8)>>>(x, pXF);            // 2
    gram2<<<dim3(32, 64, 2), 256>>>(x, y, pL, pX, pxn, pyn, 0.1f);     // 3

    // ---- blocked Cholesky step 0 ----
    potf2_inv<<<2, 256, PSMEM>>>(pL, pLI, 0);                          // 4
    {
        int rem = NBLK - 1;
        size_t panOff = (size_t)128 * NPT;
        gemmx<<<dim3(1, rem, 2), 256>>>(pL + panOff, pLI, pL + panOff, // 5
                128, NPT, NPT, NPT, LNN, LNN, LNN, 0, 0, 0,
                1, /*NT*/0, 1.f, 0, 0, 0, 0);
        size_t trailOff = (size_t)128 * (NPT + 1);
        gemmx<<<dim3(rem, rem, 2), 256>>>(pL + panOff, pL + panOff,    // 6 <- ncu
                pL + trailOff, 128, NPT, NPT, NPT, LNN, LNN, LNN, 0, 0, 0,
                1, /*NT*/0, -1.f, 1, 0, 1, 0);
    }
    // features fills ff^T rows of g_X; needed only before the TRSM sweep.
    features_k<<<dim3(1024, 1, 2), 256>>>(pw, pb, pX);                 // 7
    // pad rows (4160..4223) of g_X stay zero invariantly (.bss; all updates
    // preserve zero) — validated in R13's passing run. No zeroing launch.

    // ---- blocked Cholesky steps 1..31 ----
    for (int k = 1; k < NBLK; k++) {
        potf2_inv<<<2, 256, PSMEM>>>(pL, pLI, k);
        if (k < NBLK - 1) {
            int rem = NBLK - 1 - k;
            size_t panOff  = (size_t)(k + 1) * 128 * NPT + (size_t)k * 128;
            size_t diagOff = (size_t)k * 128 * (NPT + 1);
            gemmx<<<dim3(1, rem, 2), 256>>>(pL + panOff, pLI + diagOff, pL + panOff,
                    128, NPT, NPT, NPT, LNN, LNN, LNN, 0, 0, 0,
                    1, /*NT*/0, 1.f, 0, 0, 0, 0);
            size_t trailOff = (size_t)(k + 1) * 128 * (NPT + 1);
            gemmx<<<dim3(rem, rem, 2), 256>>>(pL + panOff, pL + panOff, pL + trailOff,
                    128, NPT, NPT, NPT, LNN, LNN, LNN, 0, 0, 0,
                    1, /*NT*/0, -1.f, 1, 0, 1, 0);
        }
    }

    // ---- build iL512 of each 512x512 diagonal super-block (4 launches) ----
    {
        long long sN = (long long)256 * (NPT + 1);
        long long tN = 128 * 128, tB = 16 * tN;
        gemmx<<<dim3(1, 1, 32), 256>>>(
                pL + (size_t)128 * NPT, pLI, pT,
                128, NPT, NPT, 128, LNN, LNN, tB, sN, sN, tN,
                16, /*NN*/1, 1.f, 0, 2, 0, 0);
        gemmx<<<dim3(1, 1, 32), 256>>>(
                pLI + (size_t)128 * NPT + 128, pT, pLI + (size_t)128 * NPT,
                128, NPT, 128, NPT, LNN, tB, LNN, sN, tN, sN,
                16, /*NN*/1, -1.f, 0, 3, 0, 0);
        long long sN2 = (long long)512 * (NPT + 1);
        long long tN2 = 256 * 256, tB2 = 8 * tN2;
        gemmx<<<dim3(2, 2, 16), 256>>>(
                pL + (size_t)256 * NPT, pLI, pT,
                256, NPT, NPT, 256, LNN, LNN, tB2, sN2, sN2, tN2,
                8, /*NN*/1, 1.f, 0, 2, 0, 0);
        gemmx<<<dim3(2, 2, 16), 256>>>(
                pLI + (size_t)256 * NPT + 256, pT, pLI + (size_t)256 * NPT,
                256, NPT, 256, NPT, LNN, tB2, LNN, sN2, tN2, sN2,
                8, /*NN*/1, -1.f, 0, 3, 0, 0);
    }

    // ---- right-TRSM in 8 super-steps of 512 columns ----
    for (int J = 0; J < 8; J++) {
        size_t col = (size_t)J * 512;
        if (J > 0) {
            gemmx<<<dim3(4, MROWS / 128, 2), 256>>>(
                    pX2, pL + col * NPT, pX + col,
                    J * 512, NPT, NPT, NPT, XNN, LNN, XNN, 0, 0, 0,
                    1, /*NT*/0, -1.f, 1, 0, 0, 0);
        }
        gemmx<<<dim3(4, MROWS / 128, 2), 256>>>(
                pX + col, pLI + col * (NPT + 1), pX2 + col,
                512, NPT, NPT, NPT, XNN, LNN, XNN, 0, 0, 0,
                1, /*NT*/0, 1.f, 0, 1, 0, 0);
    }

    // ---- mu: split-K (8 x 512), then reduce ----
    gemmx<<<dim3(8, 32, 2), 256>>>(pX2, pX2 + LNN, pMUP,
            NPT, NPT, NPT, 128, XNN, XNN, (long long)8 * NPT * 128, 0, 0, 0,
            1, /*NT*/0, 1.f, 0, 0, 0, 512);
    reduce_mu<<<dim3(1024, 1, 2), 256>>>(pMUP, out);

    // ---- local covariance channels ----
    local_k<<<dim3(4096, 1, 2), 256>>>(pX2, pXF, pxn, out);
}